// round 2
// baseline (speedup 1.0000x reference)
#include <cuda_runtime.h>
#include <math.h>

// Problem constants
#define BATCH 8
#define SLEN  2048
#define DCOL  768
#define MTOK  (BATCH * SLEN)   // 16384 tokens

// -------- scratch (allocation-free: __device__ globals) --------
__device__ float g_q  [(size_t)MTOK * DCOL];
__device__ float g_k  [(size_t)MTOK * DCOL];
__device__ float g_v  [(size_t)MTOK * DCOL];
__device__ float g_att[(size_t)MTOK * DCOL];
__device__ float g_h  [(size_t)MTOK * DCOL];
__device__ float g_s  [(size_t)BATCH * SLEN * SLEN];

// ---------------------------------------------------------------
// Tiled SGEMM: 128x128 block tile, BK=8, 256 threads, 8x8/thread.
// MODE 0: C = A @ B^T + bias                      (projection)
// MODE 1: C = relu(A @ B^T + bias)                (gate hidden)
// MODE 2: C = alpha * (A @ B^T)                   (scores)
// MODE 3: C = A @ B                               (attend: P @ V)
// MODE 4: z = A @ B^T + bias;
//         C = sigmoid(sigmoid(z)) * att * ts      (final gate)
// Batched via blockIdx.z with element strides sA/sB/sC.
// Requires: M,N % 128 == 0, K % 8 == 0, pointers 16B aligned.
// ---------------------------------------------------------------
template <int MODE>
__global__ __launch_bounds__(256) void gemm_k(
    const float* __restrict__ A, const float* __restrict__ B,
    float* __restrict__ C,
    int M, int N, int K,
    long sA, long sB, long sC,
    const float* __restrict__ bias, float alpha,
    const float* __restrict__ att, const float* __restrict__ ts)
{
    __shared__ float As[8][128];
    __shared__ float Bs[8][128];

    A += (long)blockIdx.z * sA;
    B += (long)blockIdx.z * sB;
    C += (long)blockIdx.z * sC;

    const int m0 = blockIdx.y * 128;
    const int n0 = blockIdx.x * 128;
    const int tid = threadIdx.x;
    const int tx = tid & 15;        // 0..15 -> N
    const int ty = tid >> 4;        // 0..15 -> M

    float acc[8][8] = {};

    for (int k0 = 0; k0 < K; k0 += 8) {
        // ---- load A tile [128 m x 8 k], store transposed As[k][m] ----
        {
            const int r  = tid >> 1;            // 0..127 (m within tile)
            const int ks = (tid & 1) * 4;       // 0 or 4
            float4 va = *(const float4*)&A[(long)(m0 + r) * K + (k0 + ks)];
            As[ks + 0][r] = va.x;
            As[ks + 1][r] = va.y;
            As[ks + 2][r] = va.z;
            As[ks + 3][r] = va.w;
        }
        // ---- load B tile ----
        if (MODE == 3) {
            // NN: B is [K,N] row-major; k-major already.
            const int kr = tid >> 5;            // 0..7
            const int ns = (tid & 31) * 4;      // 0..124
            *(float4*)&Bs[kr][ns] =
                *(const float4*)&B[(long)(k0 + kr) * N + (n0 + ns)];
        } else {
            // TN: B is [N,K] row-major; transpose into Bs[k][n].
            const int r  = tid >> 1;            // 0..127 (n within tile)
            const int ks = (tid & 1) * 4;
            float4 vb = *(const float4*)&B[(long)(n0 + r) * K + (k0 + ks)];
            Bs[ks + 0][r] = vb.x;
            Bs[ks + 1][r] = vb.y;
            Bs[ks + 2][r] = vb.z;
            Bs[ks + 3][r] = vb.w;
        }
        __syncthreads();

        #pragma unroll
        for (int kk = 0; kk < 8; kk++) {
            float4 a0 = *(const float4*)&As[kk][ty * 4];
            float4 a1 = *(const float4*)&As[kk][64 + ty * 4];
            float4 b0 = *(const float4*)&Bs[kk][tx * 4];
            float4 b1 = *(const float4*)&Bs[kk][64 + tx * 4];
            float av[8] = {a0.x, a0.y, a0.z, a0.w, a1.x, a1.y, a1.z, a1.w};
            float bv[8] = {b0.x, b0.y, b0.z, b0.w, b1.x, b1.y, b1.z, b1.w};
            #pragma unroll
            for (int i = 0; i < 8; i++)
                #pragma unroll
                for (int j = 0; j < 8; j++)
                    acc[i][j] = fmaf(av[i], bv[j], acc[i][j]);
        }
        __syncthreads();
    }

    // ---- epilogue ----
    #pragma unroll
    for (int ii = 0; ii < 2; ii++) {
        #pragma unroll
        for (int i = 0; i < 4; i++) {
            const int m = m0 + ii * 64 + ty * 4 + i;
            #pragma unroll
            for (int jj = 0; jj < 2; jj++) {
                const int n = n0 + jj * 64 + tx * 4;
                const long idx = (long)m * N + n;
                float4 r;
                float vv[4] = {acc[ii * 4 + i][jj * 4 + 0],
                               acc[ii * 4 + i][jj * 4 + 1],
                               acc[ii * 4 + i][jj * 4 + 2],
                               acc[ii * 4 + i][jj * 4 + 3]};
                #pragma unroll
                for (int j = 0; j < 4; j++) {
                    float x = vv[j];
                    if (MODE == 0 || MODE == 1 || MODE == 4) x += bias[n + j];
                    if (MODE == 1) x = fmaxf(x, 0.0f);
                    if (MODE == 2) x *= alpha;
                    if (MODE == 4) {
                        float g = 1.0f / (1.0f + __expf(-x));   // sigmoid(z)
                        g = 1.0f / (1.0f + __expf(-g));         // sigmoid again (faithful)
                        x = g * att[idx + j] * ts[n + j];
                    }
                    vv[j] = x;
                }
                r.x = vv[0]; r.y = vv[1]; r.z = vv[2]; r.w = vv[3];
                *(float4*)&C[idx] = r;
            }
        }
    }
}

// ---------------------------------------------------------------
// Row softmax over contiguous rows of length 2048. One block/row.
// ---------------------------------------------------------------
__global__ __launch_bounds__(256) void softmax_k(float* __restrict__ S)
{
    float* p = S + (long)blockIdx.x * SLEN;
    const int tid = threadIdx.x;
    const int lane = tid & 31;
    const int wid = tid >> 5;
    __shared__ float red[8];

    float v[8];
    float mx = -INFINITY;
    #pragma unroll
    for (int i = 0; i < 8; i++) {
        v[i] = p[tid + 256 * i];
        mx = fmaxf(mx, v[i]);
    }
    #pragma unroll
    for (int o = 16; o > 0; o >>= 1)
        mx = fmaxf(mx, __shfl_xor_sync(0xFFFFFFFFu, mx, o));
    if (lane == 0) red[wid] = mx;
    __syncthreads();
    {
        float m2 = red[lane & 7];
        #pragma unroll
        for (int o = 4; o > 0; o >>= 1)
            m2 = fmaxf(m2, __shfl_xor_sync(0xFFFFFFFFu, m2, o));
        mx = __shfl_sync(0xFFFFFFFFu, m2, 0);
    }

    float sum = 0.0f;
    #pragma unroll
    for (int i = 0; i < 8; i++) {
        v[i] = __expf(v[i] - mx);
        sum += v[i];
    }
    #pragma unroll
    for (int o = 16; o > 0; o >>= 1)
        sum += __shfl_xor_sync(0xFFFFFFFFu, sum, o);
    __syncthreads();
    if (lane == 0) red[wid] = sum;
    __syncthreads();
    {
        float s2 = red[lane & 7];
        #pragma unroll
        for (int o = 4; o > 0; o >>= 1)
            s2 += __shfl_xor_sync(0xFFFFFFFFu, s2, o);
        sum = __shfl_sync(0xFFFFFFFFu, s2, 0);
    }

    const float inv = 1.0f / sum;
    #pragma unroll
    for (int i = 0; i < 8; i++)
        p[tid + 256 * i] = v[i] * inv;
}

// ---------------------------------------------------------------
// Launch
// ---------------------------------------------------------------
extern "C" void kernel_launch(void* const* d_in, const int* in_sizes, int n_in,
                              void* d_out, int out_size)
{
    const float* query = (const float*)d_in[0];
    const float* key   = (const float*)d_in[1];
    const float* value = (const float*)d_in[2];
    const float* Wq  = (const float*)d_in[3];
    const float* bq  = (const float*)d_in[4];
    const float* Wk  = (const float*)d_in[5];
    const float* bk  = (const float*)d_in[6];
    const float* Wv  = (const float*)d_in[7];
    const float* bv  = (const float*)d_in[8];
    const float* Wg1 = (const float*)d_in[9];
    const float* bg1 = (const float*)d_in[10];
    const float* Wg2 = (const float*)d_in[11];
    const float* bg2 = (const float*)d_in[12];
    const float* ts  = (const float*)d_in[13];
    float* out = (float*)d_out;

    float *q, *k, *v, *att, *h, *s;
    cudaGetSymbolAddress((void**)&q,   g_q);
    cudaGetSymbolAddress((void**)&k,   g_k);
    cudaGetSymbolAddress((void**)&v,   g_v);
    cudaGetSymbolAddress((void**)&att, g_att);
    cudaGetSymbolAddress((void**)&h,   g_h);
    cudaGetSymbolAddress((void**)&s,   g_s);

    const dim3 blk(256);
    const dim3 gproj(DCOL / 128, MTOK / 128, 1);      // (6, 128)
    const dim3 gsc(SLEN / 128, SLEN / 128, BATCH);    // (16, 16, 8)
    const dim3 gat(DCOL / 128, SLEN / 128, BATCH);    // (6, 16, 8)

    // Q/K/V projections
    gemm_k<0><<<gproj, blk>>>(query, Wq, q, MTOK, DCOL, DCOL, 0, 0, 0, bq, 1.0f, nullptr, nullptr);
    gemm_k<0><<<gproj, blk>>>(key,   Wk, k, MTOK, DCOL, DCOL, 0, 0, 0, bk, 1.0f, nullptr, nullptr);
    gemm_k<0><<<gproj, blk>>>(value, Wv, v, MTOK, DCOL, DCOL, 0, 0, 0, bv, 1.0f, nullptr, nullptr);

    // scores = (Q @ K^T) / sqrt(D), batched
    const float scale = 1.0f / sqrtf((float)DCOL);
    gemm_k<2><<<gsc, blk>>>(q, k, s, SLEN, SLEN, DCOL,
                            (long)SLEN * DCOL, (long)SLEN * DCOL, (long)SLEN * SLEN,
                            nullptr, scale, nullptr, nullptr);

    // softmax over rows
    softmax_k<<<MTOK, 256>>>(s);

    // attended = P @ V, batched (NN)
    gemm_k<3><<<gat, blk>>>(s, v, att, SLEN, DCOL, SLEN,
                            (long)SLEN * SLEN, (long)SLEN * DCOL, (long)SLEN * DCOL,
                            nullptr, 1.0f, nullptr, nullptr);

    // gate hidden: h = relu(att @ Wg1^T + bg1)
    gemm_k<1><<<gproj, blk>>>(att, Wg1, h, MTOK, DCOL, DCOL, 0, 0, 0, bg1, 1.0f, nullptr, nullptr);

    // out = sigmoid(sigmoid(h @ Wg2^T + bg2)) * att * ts
    gemm_k<4><<<gproj, blk>>>(h, Wg2, out, MTOK, DCOL, DCOL, 0, 0, 0, bg2, 1.0f, att, ts);
}

// round 3
// speedup vs baseline: 1.0365x; 1.0365x over previous
#include <cuda_runtime.h>
#include <math.h>
#include <stdint.h>

// Problem constants
#define BATCH 8
#define SLEN  2048
#define DCOL  768
#define MTOK  (BATCH * SLEN)   // 16384 tokens

// -------- scratch (allocation-free: __device__ globals) --------
__device__ float g_q  [(size_t)MTOK * DCOL];
__device__ float g_k  [(size_t)MTOK * DCOL];
__device__ float g_v  [(size_t)MTOK * DCOL];
__device__ float g_att[(size_t)MTOK * DCOL];
__device__ float g_h  [(size_t)MTOK * DCOL];
__device__ float g_s  [(size_t)BATCH * SLEN * SLEN];

// ---------------------------------------------------------------
// tf32 helpers
// ---------------------------------------------------------------
__device__ __forceinline__ float tf32_rna(float x) {
    uint32_t u;
    asm("cvt.rna.tf32.f32 %0, %1;" : "=r"(u) : "f"(x));
    return __uint_as_float(u);
}

__device__ __forceinline__ void mma_tf32(float* c,
                                         uint32_t a0, uint32_t a1, uint32_t a2, uint32_t a3,
                                         uint32_t b0, uint32_t b1) {
    asm volatile(
        "mma.sync.aligned.m16n8k8.row.col.f32.tf32.tf32.f32 "
        "{%0,%1,%2,%3}, {%4,%5,%6,%7}, {%8,%9}, {%0,%1,%2,%3};"
        : "+f"(c[0]), "+f"(c[1]), "+f"(c[2]), "+f"(c[3])
        : "r"(a0), "r"(a1), "r"(a2), "r"(a3), "r"(b0), "r"(b1));
}

// ---------------------------------------------------------------
// Tensor-core GEMM (3xTF32 for ~fp32 accuracy).
// Block tile 128x128, BK=8, 256 threads = 8 warps (2Mx4N), warp tile 64x32.
// MODE 0: C = A @ B^T + bias                      (projection)
// MODE 1: C = relu(A @ B^T + bias)                (gate hidden)
// MODE 2: C = alpha * (A @ B^T)                   (scores)
// MODE 3: C = A @ B                               (attend: P @ V)
// MODE 4: z = A @ B^T + bias;
//         C = sigmoid(sigmoid(z)) * att * ts      (final gate)
// Batched via blockIdx.z (strides sA/sB/sC).
// Requires: M,N % 128 == 0, K % 8 == 0, pointers 16B aligned.
// ---------------------------------------------------------------
#define SPAD 136   // smem row stride in floats; 136 % 32 == 8 -> conflict-free frags

template <int MODE>
__global__ __launch_bounds__(256, 2) void gemm_tc(
    const float* __restrict__ A, const float* __restrict__ B,
    float* __restrict__ C,
    int M, int N, int K,
    long sA, long sB, long sC,
    const float* __restrict__ bias, float alpha,
    const float* __restrict__ att, const float* __restrict__ ts)
{
    __shared__ float Ah[2][8][SPAD];
    __shared__ float Al[2][8][SPAD];
    __shared__ float Bh[2][8][SPAD];
    __shared__ float Bl[2][8][SPAD];

    A += (long)blockIdx.z * sA;
    B += (long)blockIdx.z * sB;
    C += (long)blockIdx.z * sC;

    const int m0 = blockIdx.y * 128;
    const int n0 = blockIdx.x * 128;
    const int tid  = threadIdx.x;
    const int warp = tid >> 5;
    const int lane = tid & 31;
    const int wm = warp >> 2;        // 0..1 -> M offset wm*64
    const int wn = warp & 3;         // 0..3 -> N offset wn*32
    const int g  = lane >> 2;        // groupID 0..7
    const int t  = lane & 3;         // threadID_in_group 0..3

    float acc[4][4][4];
    #pragma unroll
    for (int i = 0; i < 4; i++)
        #pragma unroll
        for (int j = 0; j < 4; j++)
            #pragma unroll
            for (int c = 0; c < 4; c++) acc[i][j][c] = 0.0f;

    float4 L0, L1;   // gmem staging registers

    // ---- gmem -> regs ----
    auto ldg_tile = [&](int k0) {
        if (tid < 128) {
            const float* p = &A[(long)(m0 + tid) * K + k0];
            L0 = *(const float4*)p;
            L1 = *(const float4*)(p + 4);
        } else if (MODE == 3) {
            const int i = tid - 128;
            const int kr  = i >> 4;          // 0..7
            const int nc4 = i & 15;          // 0..15
            const float* p = &B[(long)(k0 + kr) * N + n0];
            L0 = *(const float4*)(p + nc4 * 4);
            L1 = *(const float4*)(p + (nc4 + 16) * 4);
        } else {
            const int r = tid - 128;
            const float* p = &B[(long)(n0 + r) * K + k0];
            L0 = *(const float4*)p;
            L1 = *(const float4*)(p + 4);
        }
    };

    // ---- regs -> smem (tf32 hi/lo split) ----
    auto sts_tile = [&](int b) {
        float v[8] = {L0.x, L0.y, L0.z, L0.w, L1.x, L1.y, L1.z, L1.w};
        float hi[8], lo[8];
        #pragma unroll
        for (int u = 0; u < 8; u++) {
            hi[u] = tf32_rna(v[u]);
            lo[u] = tf32_rna(v[u] - hi[u]);
        }
        if (tid < 128) {
            #pragma unroll
            for (int u = 0; u < 8; u++) {
                Ah[b][u][tid] = hi[u];
                Al[b][u][tid] = lo[u];
            }
        } else if (MODE == 3) {
            const int i = tid - 128;
            const int kr  = i >> 4;
            const int nc4 = i & 15;
            *(float4*)&Bh[b][kr][nc4 * 4]        = make_float4(hi[0], hi[1], hi[2], hi[3]);
            *(float4*)&Bh[b][kr][(nc4 + 16) * 4] = make_float4(hi[4], hi[5], hi[6], hi[7]);
            *(float4*)&Bl[b][kr][nc4 * 4]        = make_float4(lo[0], lo[1], lo[2], lo[3]);
            *(float4*)&Bl[b][kr][(nc4 + 16) * 4] = make_float4(lo[4], lo[5], lo[6], lo[7]);
        } else {
            const int r = tid - 128;
            #pragma unroll
            for (int u = 0; u < 8; u++) {
                Bh[b][u][r] = hi[u];
                Bl[b][u][r] = lo[u];
            }
        }
    };

    // ---- compute one BK=8 slab from buffer b ----
    auto compute = [&](int b) {
        uint32_t bh[4][2], bl[4][2];
        #pragma unroll
        for (int nf = 0; nf < 4; nf++) {
            const int nb = wn * 32 + nf * 8 + g;
            bh[nf][0] = __float_as_uint(Bh[b][t][nb]);
            bh[nf][1] = __float_as_uint(Bh[b][t + 4][nb]);
            bl[nf][0] = __float_as_uint(Bl[b][t][nb]);
            bl[nf][1] = __float_as_uint(Bl[b][t + 4][nb]);
        }
        #pragma unroll
        for (int mf = 0; mf < 4; mf++) {
            const int mb = wm * 64 + mf * 16 + g;
            uint32_t ah0 = __float_as_uint(Ah[b][t][mb]);
            uint32_t ah1 = __float_as_uint(Ah[b][t][mb + 8]);
            uint32_t ah2 = __float_as_uint(Ah[b][t + 4][mb]);
            uint32_t ah3 = __float_as_uint(Ah[b][t + 4][mb + 8]);
            uint32_t al0 = __float_as_uint(Al[b][t][mb]);
            uint32_t al1 = __float_as_uint(Al[b][t][mb + 8]);
            uint32_t al2 = __float_as_uint(Al[b][t + 4][mb]);
            uint32_t al3 = __float_as_uint(Al[b][t + 4][mb + 8]);
            #pragma unroll
            for (int nf = 0; nf < 4; nf++) {
                mma_tf32(acc[mf][nf], ah0, ah1, ah2, ah3, bl[nf][0], bl[nf][1]);
                mma_tf32(acc[mf][nf], al0, al1, al2, al3, bh[nf][0], bh[nf][1]);
                mma_tf32(acc[mf][nf], ah0, ah1, ah2, ah3, bh[nf][0], bh[nf][1]);
            }
        }
    };

    // ---- pipelined main loop ----
    ldg_tile(0);
    sts_tile(0);
    __syncthreads();
    int buf = 0;
    for (int k0 = 0; k0 < K; k0 += 8) {
        const bool nxt = (k0 + 8) < K;
        if (nxt) ldg_tile(k0 + 8);
        compute(buf);
        if (nxt) sts_tile(buf ^ 1);
        __syncthreads();
        buf ^= 1;
    }

    // ---- epilogue ----
    #pragma unroll
    for (int mf = 0; mf < 4; mf++) {
        #pragma unroll
        for (int nf = 0; nf < 4; nf++) {
            const int m = m0 + wm * 64 + mf * 16 + g;
            const int n = n0 + wn * 32 + nf * 8 + 2 * t;
            float* c = acc[mf][nf];
            #pragma unroll
            for (int half = 0; half < 2; half++) {
                const int mm = m + half * 8;
                const long idx = (long)mm * N + n;
                float x0 = c[half * 2 + 0];
                float x1 = c[half * 2 + 1];
                if (MODE == 0 || MODE == 1 || MODE == 4) { x0 += bias[n]; x1 += bias[n + 1]; }
                if (MODE == 1) { x0 = fmaxf(x0, 0.0f); x1 = fmaxf(x1, 0.0f); }
                if (MODE == 2) { x0 *= alpha; x1 *= alpha; }
                if (MODE == 4) {
                    float g0 = 1.0f / (1.0f + __expf(-x0));
                    g0 = 1.0f / (1.0f + __expf(-g0));
                    float g1 = 1.0f / (1.0f + __expf(-x1));
                    g1 = 1.0f / (1.0f + __expf(-g1));
                    x0 = g0 * att[idx]     * ts[n];
                    x1 = g1 * att[idx + 1] * ts[n + 1];
                }
                *(float2*)&C[idx] = make_float2(x0, x1);
            }
        }
    }
}

// ---------------------------------------------------------------
// Row softmax over contiguous rows of length 2048. One block/row.
// ---------------------------------------------------------------
__global__ __launch_bounds__(256) void softmax_k(float* __restrict__ S)
{
    float* p = S + (long)blockIdx.x * SLEN;
    const int tid = threadIdx.x;
    const int lane = tid & 31;
    const int wid = tid >> 5;
    __shared__ float red[8];

    float v[8];
    float mx = -INFINITY;
    #pragma unroll
    for (int i = 0; i < 8; i++) {
        v[i] = p[tid + 256 * i];
        mx = fmaxf(mx, v[i]);
    }
    #pragma unroll
    for (int o = 16; o > 0; o >>= 1)
        mx = fmaxf(mx, __shfl_xor_sync(0xFFFFFFFFu, mx, o));
    if (lane == 0) red[wid] = mx;
    __syncthreads();
    {
        float m2 = red[lane & 7];
        #pragma unroll
        for (int o = 4; o > 0; o >>= 1)
            m2 = fmaxf(m2, __shfl_xor_sync(0xFFFFFFFFu, m2, o));
        mx = __shfl_sync(0xFFFFFFFFu, m2, 0);
    }

    float sum = 0.0f;
    #pragma unroll
    for (int i = 0; i < 8; i++) {
        v[i] = __expf(v[i] - mx);
        sum += v[i];
    }
    #pragma unroll
    for (int o = 16; o > 0; o >>= 1)
        sum += __shfl_xor_sync(0xFFFFFFFFu, sum, o);
    __syncthreads();
    if (lane == 0) red[wid] = sum;
    __syncthreads();
    {
        float s2 = red[lane & 7];
        #pragma unroll
        for (int o = 4; o > 0; o >>= 1)
            s2 += __shfl_xor_sync(0xFFFFFFFFu, s2, o);
        sum = __shfl_sync(0xFFFFFFFFu, s2, 0);
    }

    const float inv = 1.0f / sum;
    #pragma unroll
    for (int i = 0; i < 8; i++)
        p[tid + 256 * i] = v[i] * inv;
}

// ---------------------------------------------------------------
// Launch
// ---------------------------------------------------------------
extern "C" void kernel_launch(void* const* d_in, const int* in_sizes, int n_in,
                              void* d_out, int out_size)
{
    const float* query = (const float*)d_in[0];
    const float* key   = (const float*)d_in[1];
    const float* value = (const float*)d_in[2];
    const float* Wq  = (const float*)d_in[3];
    const float* bq  = (const float*)d_in[4];
    const float* Wk  = (const float*)d_in[5];
    const float* bk  = (const float*)d_in[6];
    const float* Wv  = (const float*)d_in[7];
    const float* bv  = (const float*)d_in[8];
    const float* Wg1 = (const float*)d_in[9];
    const float* bg1 = (const float*)d_in[10];
    const float* Wg2 = (const float*)d_in[11];
    const float* bg2 = (const float*)d_in[12];
    const float* ts  = (const float*)d_in[13];
    float* out = (float*)d_out;

    float *q, *k, *v, *att, *h, *s;
    cudaGetSymbolAddress((void**)&q,   g_q);
    cudaGetSymbolAddress((void**)&k,   g_k);
    cudaGetSymbolAddress((void**)&v,   g_v);
    cudaGetSymbolAddress((void**)&att, g_att);
    cudaGetSymbolAddress((void**)&h,   g_h);
    cudaGetSymbolAddress((void**)&s,   g_s);

    const dim3 blk(256);
    const dim3 gproj(DCOL / 128, MTOK / 128, 1);      // (6, 128)
    const dim3 gsc(SLEN / 128, SLEN / 128, BATCH);    // (16, 16, 8)
    const dim3 gat(DCOL / 128, SLEN / 128, BATCH);    // (6, 16, 8)

    // Q/K/V projections
    gemm_tc<0><<<gproj, blk>>>(query, Wq, q, MTOK, DCOL, DCOL, 0, 0, 0, bq, 1.0f, nullptr, nullptr);
    gemm_tc<0><<<gproj, blk>>>(key,   Wk, k, MTOK, DCOL, DCOL, 0, 0, 0, bk, 1.0f, nullptr, nullptr);
    gemm_tc<0><<<gproj, blk>>>(value, Wv, v, MTOK, DCOL, DCOL, 0, 0, 0, bv, 1.0f, nullptr, nullptr);

    // scores = (Q @ K^T) / sqrt(D), batched
    const float scale = 1.0f / sqrtf((float)DCOL);
    gemm_tc<2><<<gsc, blk>>>(q, k, s, SLEN, SLEN, DCOL,
                             (long)SLEN * DCOL, (long)SLEN * DCOL, (long)SLEN * SLEN,
                             nullptr, scale, nullptr, nullptr);

    // softmax over rows
    softmax_k<<<MTOK, 256>>>(s);

    // attended = P @ V, batched (NN)
    gemm_tc<3><<<gat, blk>>>(s, v, att, SLEN, DCOL, SLEN,
                             (long)SLEN * SLEN, (long)SLEN * DCOL, (long)SLEN * DCOL,
                             nullptr, 1.0f, nullptr, nullptr);

    // gate hidden: h = relu(att @ Wg1^T + bg1)
    gemm_tc<1><<<gproj, blk>>>(att, Wg1, h, MTOK, DCOL, DCOL, 0, 0, 0, bg1, 1.0f, nullptr, nullptr);

    // out = sigmoid(sigmoid(h @ Wg2^T + bg2)) * att * ts
    gemm_tc<4><<<gproj, blk>>>(h, Wg2, out, MTOK, DCOL, DCOL, 0, 0, 0, bg2, 1.0f, att, ts);
}

// round 5
// speedup vs baseline: 2.0467x; 1.9746x over previous
#include <cuda_runtime.h>
#include <cuda_bf16.h>
#include <math.h>
#include <stdint.h>

#define BATCH 8
#define SLEN  2048
#define DCOL  768
#define MTOK  (BATCH*SLEN)   // 16384

typedef __nv_bfloat16 bf16;

// ---------------- scratch (__device__ globals, no allocs) ----------------
__device__ bf16 g_xh[3][(size_t)MTOK*DCOL];   // split inputs q,k,v
__device__ bf16 g_xl[3][(size_t)MTOK*DCOL];
__device__ bf16 g_wh[5][(size_t)DCOL*DCOL];   // split weights
__device__ bf16 g_wl[5][(size_t)DCOL*DCOL];
__device__ bf16 g_ah[5][(size_t)MTOK*DCOL];   // 0=q 1=k 2=v 3=att 4=h (hi)
__device__ bf16 g_al[5][(size_t)MTOK*DCOL];
__device__ bf16 g_vth[(size_t)MTOK*DCOL];     // V^T per batch [768][2048]
__device__ bf16 g_vtl[(size_t)MTOK*DCOL];
__device__ float g_att[(size_t)MTOK*DCOL];    // attended fp32 (final gate)
__device__ float g_s  [(size_t)BATCH*SLEN*SLEN];
__device__ bf16 g_ph[(size_t)BATCH*SLEN*SLEN];
__device__ bf16 g_pl[(size_t)BATCH*SLEN*SLEN];

// ---------------- PTX helpers (portable sm_80+ ISA only) ----------------
__device__ __forceinline__ uint32_t smem_u32(const void* p) {
    uint32_t a;
    asm("{ .reg .u64 t; cvta.to.shared.u64 t, %1; cvt.u32.u64 %0, t; }" : "=r"(a) : "l"(p));
    return a;
}
#define CP16(dst, src) \
    asm volatile("cp.async.cg.shared.global [%0], [%1], 16;" :: "r"(dst), "l"(src) : "memory")
#define CPCOMMIT() asm volatile("cp.async.commit_group;" ::: "memory")
#define CPWAIT1()  asm volatile("cp.async.wait_group 1;" ::: "memory")
#define CPWAIT0()  asm volatile("cp.async.wait_group 0;" ::: "memory")

__device__ __forceinline__ void ldsm4(uint32_t& r0, uint32_t& r1, uint32_t& r2, uint32_t& r3,
                                      uint32_t addr) {
    asm volatile("ldmatrix.sync.aligned.m8n8.x4.shared.b16 {%0,%1,%2,%3}, [%4];"
                 : "=r"(r0), "=r"(r1), "=r"(r2), "=r"(r3) : "r"(addr));
}
__device__ __forceinline__ void mma_bf16(float* c,
                                         uint32_t a0, uint32_t a1, uint32_t a2, uint32_t a3,
                                         uint32_t b0, uint32_t b1) {
    asm volatile(
        "mma.sync.aligned.m16n8k16.row.col.f32.bf16.bf16.f32 "
        "{%0,%1,%2,%3}, {%4,%5,%6,%7}, {%8,%9}, {%0,%1,%2,%3};"
        : "+f"(c[0]), "+f"(c[1]), "+f"(c[2]), "+f"(c[3])
        : "r"(a0), "r"(a1), "r"(a2), "r"(a3), "r"(b0), "r"(b1));
}

// smem: 2 stages; per stage 4 arrays (Ah, Al, Bh, Bl) of 128 rows x 80B (64B data + 16B pad)
#define ROWB   80
#define ARR    (128 * ROWB)       // 10240
#define STAGE  (4 * ARR)          // 40960
#define SMEM_BYTES (2 * STAGE)    // 81920

// ---------------------------------------------------------------
// bf16 3-term mma.sync GEMM: C[M,N] = A[M,K] @ B[N,K]^T
// Tile 128x128, BK=32, 256 threads (8 warps, 2Mx4N, warp tile 64x32).
// MODE 0: +bias -> Ch/Cl        MODE 1: relu(+bias) -> Ch/Cl
// MODE 2: *alpha -> Cf          MODE 3: plain -> Cf + Ch/Cl
// MODE 4: sig(sig(+bias)) * att * ts -> Cf
// ---------------------------------------------------------------
template <int MODE>
__global__ __launch_bounds__(256, 1) void gemm_m(
    const bf16* __restrict__ Ah, const bf16* __restrict__ Al,
    const bf16* __restrict__ Bh, const bf16* __restrict__ Bl,
    int M, int N, int K, long sA, long sB, long sC,
    const float* __restrict__ bias, float alpha,
    float* __restrict__ Cf, bf16* __restrict__ Ch, bf16* __restrict__ Cl,
    const float* __restrict__ att, const float* __restrict__ ts)
{
    extern __shared__ char smem[];
    const uint32_t sb = smem_u32(smem);
    const int tid  = threadIdx.x;
    const int warp = tid >> 5;
    const int lane = tid & 31;
    const int wm = warp >> 2;          // 0..1
    const int wn = warp & 3;           // 0..3
    const int g  = lane >> 2;
    const int t  = lane & 3;
    const int z  = blockIdx.z;
    const int m0 = blockIdx.y * 128;
    const int n0 = blockIdx.x * 128;

    const bf16* aH = Ah + (long)z * sA;
    const bf16* aL = Al + (long)z * sA;
    const bf16* bH = Bh + (long)z * sB;
    const bf16* bL = Bl + (long)z * sB;

    float acc[4][4][4];
    #pragma unroll
    for (int i = 0; i < 4; i++)
        #pragma unroll
        for (int j = 0; j < 4; j++)
            #pragma unroll
            for (int c = 0; c < 4; c++) acc[i][j][c] = 0.0f;

    // ---- async slab loader: 4 arrays x 512 chunks of 16B ----
    auto load_slab = [&](int slab, int s) {
        const int k0 = slab * 32;
        const uint32_t base = sb + s * STAGE;
        #pragma unroll
        for (int j = 0; j < 2; j++) {
            const int ch  = tid + 256 * j;       // 0..511
            const int row = ch >> 2;
            const int c   = ch & 3;
            const uint32_t so = (uint32_t)(row * ROWB + c * 16);
            const long ao = (long)(m0 + row) * K + k0 + c * 8;
            const long bo = (long)(n0 + row) * K + k0 + c * 8;
            CP16(base + 0 * ARR + so, aH + ao);
            CP16(base + 1 * ARR + so, aL + ao);
            CP16(base + 2 * ARR + so, bH + bo);
            CP16(base + 3 * ARR + so, bL + bo);
        }
    };

    // ---- compute one BK=32 slab from stage s ----
    auto compute = [&](int s) {
        const uint32_t bAh = sb + s * STAGE;
        const uint32_t bAl = bAh + ARR;
        const uint32_t bBh = bAh + 2 * ARR;
        const uint32_t bBl = bAh + 3 * ARR;
        #pragma unroll
        for (int kk = 0; kk < 2; kk++) {
            // B fragments: 4 n-tiles via 2 ldmatrix.x4 (hi) + 2 (lo)
            uint32_t bh[4][2], bl[4][2];
            #pragma unroll
            for (int np = 0; np < 2; np++) {
                const uint32_t row = wn * 32 + np * 16 + ((lane >> 4) & 1) * 8 + (lane & 7);
                const uint32_t off = row * ROWB + kk * 32 + ((lane >> 3) & 1) * 16;
                ldsm4(bh[np*2][0], bh[np*2][1], bh[np*2+1][0], bh[np*2+1][1], bBh + off);
                ldsm4(bl[np*2][0], bl[np*2][1], bl[np*2+1][0], bl[np*2+1][1], bBl + off);
            }
            // A fragments per m-tile, 3-term mma
            #pragma unroll
            for (int mt = 0; mt < 4; mt++) {
                const uint32_t row = wm * 64 + mt * 16 + (lane & 15);
                const uint32_t off = row * ROWB + kk * 32 + (lane >> 4) * 16;
                uint32_t ah0, ah1, ah2, ah3, al0, al1, al2, al3;
                ldsm4(ah0, ah1, ah2, ah3, bAh + off);
                ldsm4(al0, al1, al2, al3, bAl + off);
                #pragma unroll
                for (int nt = 0; nt < 4; nt++) {
                    mma_bf16(acc[mt][nt], ah0, ah1, ah2, ah3, bh[nt][0], bh[nt][1]);
                    mma_bf16(acc[mt][nt], ah0, ah1, ah2, ah3, bl[nt][0], bl[nt][1]);
                    mma_bf16(acc[mt][nt], al0, al1, al2, al3, bh[nt][0], bh[nt][1]);
                }
            }
        }
    };

    const int iters = K / 32;          // >= 24 always
    load_slab(0, 0); CPCOMMIT();
    load_slab(1, 1); CPCOMMIT();
    CPWAIT1();
    __syncthreads();

    for (int i = 0; i < iters; i++) {
        const int s = i & 1;
        compute(s);
        __syncthreads();
        if (i + 2 < iters) { load_slab(i + 2, s); CPCOMMIT(); }
        if (i + 1 < iters) {
            if (i + 2 < iters) CPWAIT1(); else CPWAIT0();
            __syncthreads();
        }
    }

    // ---- epilogue from registers ----
    #pragma unroll
    for (int mt = 0; mt < 4; mt++) {
        #pragma unroll
        for (int nt = 0; nt < 4; nt++) {
            const int m = m0 + wm * 64 + mt * 16 + g;
            const int n = n0 + wn * 32 + nt * 8 + 2 * t;
            float* c = acc[mt][nt];
            #pragma unroll
            for (int half = 0; half < 2; half++) {
                const int mm = m + half * 8;
                const long idx = (long)mm * N + n;
                float x0 = c[half * 2 + 0];
                float x1 = c[half * 2 + 1];
                if (MODE == 0 || MODE == 1 || MODE == 4) { x0 += bias[n]; x1 += bias[n + 1]; }
                if (MODE == 1) { x0 = fmaxf(x0, 0.0f); x1 = fmaxf(x1, 0.0f); }
                if (MODE == 2) { x0 *= alpha; x1 *= alpha; }
                if (MODE == 4) {
                    float g0 = 1.0f / (1.0f + __expf(-x0));
                    g0 = 1.0f / (1.0f + __expf(-g0));
                    float g1 = 1.0f / (1.0f + __expf(-x1));
                    g1 = 1.0f / (1.0f + __expf(-g1));
                    x0 = g0 * att[idx]     * ts[n];
                    x1 = g1 * att[idx + 1] * ts[n + 1];
                }
                if (MODE == 2 || MODE == 3 || MODE == 4)
                    *(float2*)&Cf[(long)z * sC + idx] = make_float2(x0, x1);
                if (MODE == 0 || MODE == 1 || MODE == 3) {
                    bf16 h0 = __float2bfloat16_rn(x0);
                    bf16 h1 = __float2bfloat16_rn(x1);
                    bf16 l0 = __float2bfloat16_rn(x0 - __bfloat162float(h0));
                    bf16 l1 = __float2bfloat16_rn(x1 - __bfloat162float(h1));
                    uint32_t hw = (uint32_t)__bfloat16_as_ushort(h0)
                                | ((uint32_t)__bfloat16_as_ushort(h1) << 16);
                    uint32_t lw = (uint32_t)__bfloat16_as_ushort(l0)
                                | ((uint32_t)__bfloat16_as_ushort(l1) << 16);
                    *(uint32_t*)&Ch[(long)z * sC + idx] = hw;
                    *(uint32_t*)&Cl[(long)z * sC + idx] = lw;
                }
            }
        }
    }
}

// ---------------- fp32 -> bf16 hi/lo split ----------------
__global__ __launch_bounds__(256) void split_k(const float* __restrict__ x,
                                               bf16* __restrict__ hi, bf16* __restrict__ lo,
                                               long n)
{
    long i = ((long)blockIdx.x * 256 + threadIdx.x) * 4;
    if (i >= n) return;
    float4 v = *(const float4*)&x[i];
    float a[4] = {v.x, v.y, v.z, v.w};
    uint32_t hw[2], lw[2];
    #pragma unroll
    for (int p = 0; p < 2; p++) {
        bf16 h0 = __float2bfloat16_rn(a[2*p]);
        bf16 h1 = __float2bfloat16_rn(a[2*p+1]);
        bf16 l0 = __float2bfloat16_rn(a[2*p]   - __bfloat162float(h0));
        bf16 l1 = __float2bfloat16_rn(a[2*p+1] - __bfloat162float(h1));
        hw[p] = (uint32_t)__bfloat16_as_ushort(h0) | ((uint32_t)__bfloat16_as_ushort(h1) << 16);
        lw[p] = (uint32_t)__bfloat16_as_ushort(l0) | ((uint32_t)__bfloat16_as_ushort(l1) << 16);
    }
    *(uint2*)&hi[i] = make_uint2(hw[0], hw[1]);
    *(uint2*)&lo[i] = make_uint2(lw[0], lw[1]);
}

// ---------------- V transpose (per batch): [S,D] -> [D,S] ----------------
__global__ __launch_bounds__(256) void transp_k(const bf16* __restrict__ vh,
                                                const bf16* __restrict__ vl,
                                                bf16* __restrict__ oh, bf16* __restrict__ ol)
{
    __shared__ bf16 th[32][33], tl[32][33];
    const int b = blockIdx.z;
    const int d0 = blockIdx.x * 32, s0 = blockIdx.y * 32;
    const int tx = threadIdx.x, ty = threadIdx.y;
    #pragma unroll
    for (int j = 0; j < 32; j += 8) {
        const long src = ((long)b * SLEN + s0 + ty + j) * DCOL + d0 + tx;
        th[ty + j][tx] = vh[src];
        tl[ty + j][tx] = vl[src];
    }
    __syncthreads();
    #pragma unroll
    for (int j = 0; j < 32; j += 8) {
        const long dst = ((long)b * DCOL + d0 + ty + j) * SLEN + s0 + tx;
        oh[dst] = th[tx][ty + j];
        ol[dst] = tl[tx][ty + j];
    }
}

// ---------------- row softmax (2048) -> bf16 hi/lo P ----------------
__global__ __launch_bounds__(256) void softmax_k(const float* __restrict__ S,
                                                 bf16* __restrict__ ph, bf16* __restrict__ pl)
{
    const float* p = S + (long)blockIdx.x * SLEN;
    bf16* oh = ph + (long)blockIdx.x * SLEN;
    bf16* ol = pl + (long)blockIdx.x * SLEN;
    const int tid = threadIdx.x;
    const int lane = tid & 31, wid = tid >> 5;
    __shared__ float red[8];

    float v[8];
    float mx = -INFINITY;
    #pragma unroll
    for (int i = 0; i < 8; i++) { v[i] = p[tid + 256 * i]; mx = fmaxf(mx, v[i]); }
    #pragma unroll
    for (int o = 16; o > 0; o >>= 1) mx = fmaxf(mx, __shfl_xor_sync(~0u, mx, o));
    if (lane == 0) red[wid] = mx;
    __syncthreads();
    { float m2 = red[lane & 7];
      #pragma unroll
      for (int o = 4; o > 0; o >>= 1) m2 = fmaxf(m2, __shfl_xor_sync(~0u, m2, o));
      mx = __shfl_sync(~0u, m2, 0); }
    float sum = 0.0f;
    #pragma unroll
    for (int i = 0; i < 8; i++) { v[i] = __expf(v[i] - mx); sum += v[i]; }
    #pragma unroll
    for (int o = 16; o > 0; o >>= 1) sum += __shfl_xor_sync(~0u, sum, o);
    __syncthreads();
    if (lane == 0) red[wid] = sum;
    __syncthreads();
    { float s2 = red[lane & 7];
      #pragma unroll
      for (int o = 4; o > 0; o >>= 1) s2 += __shfl_xor_sync(~0u, s2, o);
      sum = __shfl_sync(~0u, s2, 0); }
    const float inv = 1.0f / sum;
    #pragma unroll
    for (int i = 0; i < 8; i++) {
        float r = v[i] * inv;
        bf16 h = __float2bfloat16_rn(r);
        oh[tid + 256 * i] = h;
        ol[tid + 256 * i] = __float2bfloat16_rn(r - __bfloat162float(h));
    }
}

// ---------------------------------------------------------------
extern "C" void kernel_launch(void* const* d_in, const int* in_sizes, int n_in,
                              void* d_out, int out_size)
{
    const float* query = (const float*)d_in[0];
    const float* key   = (const float*)d_in[1];
    const float* value = (const float*)d_in[2];
    const float* W[5]  = {(const float*)d_in[3], (const float*)d_in[5], (const float*)d_in[7],
                          (const float*)d_in[9], (const float*)d_in[11]};
    const float* bq  = (const float*)d_in[4];
    const float* bk  = (const float*)d_in[6];
    const float* bv  = (const float*)d_in[8];
    const float* bg1 = (const float*)d_in[10];
    const float* bg2 = (const float*)d_in[12];
    const float* ts  = (const float*)d_in[13];
    float* out = (float*)d_out;

    bf16 *xh, *xl, *wh, *wl, *ah, *al, *vth, *vtl, *ph, *pl;
    float *attf, *sf;
    cudaGetSymbolAddress((void**)&xh,  g_xh);
    cudaGetSymbolAddress((void**)&xl,  g_xl);
    cudaGetSymbolAddress((void**)&wh,  g_wh);
    cudaGetSymbolAddress((void**)&wl,  g_wl);
    cudaGetSymbolAddress((void**)&ah,  g_ah);
    cudaGetSymbolAddress((void**)&al,  g_al);
    cudaGetSymbolAddress((void**)&vth, g_vth);
    cudaGetSymbolAddress((void**)&vtl, g_vtl);
    cudaGetSymbolAddress((void**)&attf, g_att);
    cudaGetSymbolAddress((void**)&sf,   g_s);
    cudaGetSymbolAddress((void**)&ph,  g_ph);
    cudaGetSymbolAddress((void**)&pl,  g_pl);

    cudaFuncSetAttribute(gemm_m<0>, cudaFuncAttributeMaxDynamicSharedMemorySize, SMEM_BYTES);
    cudaFuncSetAttribute(gemm_m<1>, cudaFuncAttributeMaxDynamicSharedMemorySize, SMEM_BYTES);
    cudaFuncSetAttribute(gemm_m<2>, cudaFuncAttributeMaxDynamicSharedMemorySize, SMEM_BYTES);
    cudaFuncSetAttribute(gemm_m<3>, cudaFuncAttributeMaxDynamicSharedMemorySize, SMEM_BYTES);
    cudaFuncSetAttribute(gemm_m<4>, cudaFuncAttributeMaxDynamicSharedMemorySize, SMEM_BYTES);

    const size_t NX = (size_t)MTOK * DCOL;
    const size_t NW = (size_t)DCOL * DCOL;

    // 1) split inputs + weights to bf16 hi/lo
    const float* xin[3] = {query, key, value};
    for (int i = 0; i < 3; i++)
        split_k<<<(int)(NX / 4 / 256), 256>>>(xin[i], xh + i * NX, xl + i * NX, (long)NX);
    for (int i = 0; i < 5; i++)
        split_k<<<(int)((NW / 4 + 255) / 256), 256>>>(W[i], wh + i * NW, wl + i * NW, (long)NW);

    const dim3 blk(256);
    const dim3 gproj(DCOL / 128, MTOK / 128, 1);
    const dim3 gsc(SLEN / 128, SLEN / 128, BATCH);
    const dim3 gat(DCOL / 128, SLEN / 128, BATCH);

    // 2) Q/K/V projections
    const float* bias3[3] = {bq, bk, bv};
    for (int i = 0; i < 3; i++)
        gemm_m<0><<<gproj, blk, SMEM_BYTES>>>(
            xh + i * NX, xl + i * NX, wh + i * NW, wl + i * NW,
            MTOK, DCOL, DCOL, 0, 0, 0, bias3[i], 1.0f,
            nullptr, ah + i * NX, al + i * NX, nullptr, nullptr);

    // 3) transpose V
    transp_k<<<dim3(DCOL / 32, SLEN / 32, BATCH), dim3(32, 8)>>>(
        ah + 2 * NX, al + 2 * NX, vth, vtl);

    // 4) scores = (Q @ K^T) * scale
    const float scale = 1.0f / sqrtf((float)DCOL);
    gemm_m<2><<<gsc, blk, SMEM_BYTES>>>(
        ah + 0 * NX, al + 0 * NX, ah + 1 * NX, al + 1 * NX,
        SLEN, SLEN, DCOL, (long)SLEN * DCOL, (long)SLEN * DCOL, (long)SLEN * SLEN,
        nullptr, scale, sf, nullptr, nullptr, nullptr, nullptr);

    // 5) softmax -> P hi/lo
    softmax_k<<<MTOK, 256>>>(sf, ph, pl);

    // 6) attended = P @ V^T(transposed V)
    gemm_m<3><<<gat, blk, SMEM_BYTES>>>(
        ph, pl, vth, vtl,
        SLEN, DCOL, SLEN, (long)SLEN * SLEN, (long)DCOL * SLEN, (long)SLEN * DCOL,
        nullptr, 1.0f, attf, ah + 3 * NX, al + 3 * NX, nullptr, nullptr);

    // 7) h = relu(att @ Wg1^T + bg1)
    gemm_m<1><<<gproj, blk, SMEM_BYTES>>>(
        ah + 3 * NX, al + 3 * NX, wh + 3 * NW, wl + 3 * NW,
        MTOK, DCOL, DCOL, 0, 0, 0, bg1, 1.0f,
        nullptr, ah + 4 * NX, al + 4 * NX, nullptr, nullptr);

    // 8) out = sig(sig(h @ Wg2^T + bg2)) * att * ts
    gemm_m<4><<<gproj, blk, SMEM_BYTES>>>(
        ah + 4 * NX, al + 4 * NX, wh + 4 * NW, wl + 4 * NW,
        MTOK, DCOL, DCOL, 0, 0, 0, bg2, 1.0f,
        out, nullptr, nullptr, attf, ts);
}

// round 6
// speedup vs baseline: 2.6621x; 1.3007x over previous
#include <cuda_runtime.h>
#include <cuda_bf16.h>
#include <math.h>
#include <stdint.h>

#define BATCH 8
#define SLEN  2048
#define DCOL  768
#define MTOK  (BATCH*SLEN)   // 16384

typedef __nv_bfloat16 bf16;

// ---------------- scratch (__device__ globals, no allocs) ----------------
__device__ bf16 g_xh[3][(size_t)MTOK*DCOL];   // split inputs q,k,v
__device__ bf16 g_xl[3][(size_t)MTOK*DCOL];
__device__ bf16 g_wh[5][(size_t)DCOL*DCOL];   // split weights
__device__ bf16 g_wl[5][(size_t)DCOL*DCOL];
__device__ bf16 g_ah[5][(size_t)MTOK*DCOL];   // 0=q 1=k 2=v 3=att 4=h (hi)
__device__ bf16 g_al[5][(size_t)MTOK*DCOL];
__device__ bf16 g_vth[(size_t)MTOK*DCOL];     // V^T per batch [768][2048]
__device__ bf16 g_vtl[(size_t)MTOK*DCOL];
__device__ float g_att[(size_t)MTOK*DCOL];    // attended fp32 (final gate)
__device__ float g_s  [(size_t)BATCH*SLEN*SLEN];
__device__ bf16 g_ph[(size_t)BATCH*SLEN*SLEN];
__device__ bf16 g_pl[(size_t)BATCH*SLEN*SLEN];

// ---------------- PTX helpers (portable sm_80+ ISA only) ----------------
__device__ __forceinline__ uint32_t smem_u32(const void* p) {
    uint32_t a;
    asm("{ .reg .u64 t; cvta.to.shared.u64 t, %1; cvt.u32.u64 %0, t; }" : "=r"(a) : "l"(p));
    return a;
}
#define CP16(dst, src) \
    asm volatile("cp.async.cg.shared.global [%0], [%1], 16;" :: "r"(dst), "l"(src) : "memory")
#define CPCOMMIT() asm volatile("cp.async.commit_group;" ::: "memory")
#define CPWAIT1()  asm volatile("cp.async.wait_group 1;" ::: "memory")
#define CPWAIT0()  asm volatile("cp.async.wait_group 0;" ::: "memory")

__device__ __forceinline__ void ldsm4(uint32_t& r0, uint32_t& r1, uint32_t& r2, uint32_t& r3,
                                      uint32_t addr) {
    asm volatile("ldmatrix.sync.aligned.m8n8.x4.shared.b16 {%0,%1,%2,%3}, [%4];"
                 : "=r"(r0), "=r"(r1), "=r"(r2), "=r"(r3) : "r"(addr));
}
__device__ __forceinline__ void mma_bf16(float* c,
                                         uint32_t a0, uint32_t a1, uint32_t a2, uint32_t a3,
                                         uint32_t b0, uint32_t b1) {
    asm volatile(
        "mma.sync.aligned.m16n8k16.row.col.f32.bf16.bf16.f32 "
        "{%0,%1,%2,%3}, {%4,%5,%6,%7}, {%8,%9}, {%0,%1,%2,%3};"
        : "+f"(c[0]), "+f"(c[1]), "+f"(c[2]), "+f"(c[3])
        : "r"(a0), "r"(a1), "r"(a2), "r"(a3), "r"(b0), "r"(b1));
}

// smem: 2 stages; per stage 4 arrays (Ah, Al, Bh, Bl) of 128 rows x 80B
#define ROWB   80
#define ARR    (128 * ROWB)       // 10240
#define STAGE  (4 * ARR)          // 40960
#define SMEM_BYTES (2 * STAGE)    // 81920

// ---------------------------------------------------------------
// bf16 mma.sync GEMM: C[M,N] = A[M,K] @ B[N,K]^T
// TERMS=3: hi*hi + hi*lo + lo*hi (fp32-class)   TERMS=1: hi*hi (bf16-class)
// Tile 128x128, BK=32, 256 threads (8 warps, 2Mx4N).
// MODE 0: +bias -> Ch/Cl        MODE 1: relu(+bias) -> Ch only
// MODE 2: *alpha -> Cf          MODE 3: plain -> Cf + Ch/Cl
// MODE 4: sig(sig(+bias)) * att * ts -> Cf
// ---------------------------------------------------------------
template <int MODE, int TERMS>
__global__ __launch_bounds__(256, 2) void gemm_m(
    const bf16* __restrict__ Ah, const bf16* __restrict__ Al,
    const bf16* __restrict__ Bh, const bf16* __restrict__ Bl,
    int M, int N, int K, long sA, long sB, long sC,
    const float* __restrict__ bias, float alpha,
    float* __restrict__ Cf, bf16* __restrict__ Ch, bf16* __restrict__ Cl,
    const float* __restrict__ att, const float* __restrict__ ts)
{
    extern __shared__ char smem[];
    const uint32_t sb = smem_u32(smem);
    const int tid  = threadIdx.x;
    const int warp = tid >> 5;
    const int lane = tid & 31;
    const int wm = warp >> 2;          // 0..1
    const int wn = warp & 3;           // 0..3
    const int g  = lane >> 2;
    const int t  = lane & 3;
    const int z  = blockIdx.z;
    const int m0 = blockIdx.y * 128;
    const int n0 = blockIdx.x * 128;

    const bf16* aH = Ah + (long)z * sA;
    const bf16* aL = Al + (long)z * sA;
    const bf16* bH = Bh + (long)z * sB;
    const bf16* bL = Bl + (long)z * sB;

    float acc[4][4][4];
    #pragma unroll
    for (int i = 0; i < 4; i++)
        #pragma unroll
        for (int j = 0; j < 4; j++)
            #pragma unroll
            for (int c = 0; c < 4; c++) acc[i][j][c] = 0.0f;

    // ---- async slab loader ----
    auto load_slab = [&](int slab, int s) {
        const int k0 = slab * 32;
        const uint32_t base = sb + s * STAGE;
        #pragma unroll
        for (int j = 0; j < 2; j++) {
            const int ch  = tid + 256 * j;       // 0..511
            const int row = ch >> 2;
            const int c   = ch & 3;
            const uint32_t so = (uint32_t)(row * ROWB + c * 16);
            const long ao = (long)(m0 + row) * K + k0 + c * 8;
            const long bo = (long)(n0 + row) * K + k0 + c * 8;
            CP16(base + 0 * ARR + so, aH + ao);
            CP16(base + 2 * ARR + so, bH + bo);
            if (TERMS == 3) {
                CP16(base + 1 * ARR + so, aL + ao);
                CP16(base + 3 * ARR + so, bL + bo);
            }
        }
    };

    // ---- compute one BK=32 slab from stage s ----
    auto compute = [&](int s) {
        const uint32_t bAh = sb + s * STAGE;
        const uint32_t bAl = bAh + ARR;
        const uint32_t bBh = bAh + 2 * ARR;
        const uint32_t bBl = bAh + 3 * ARR;
        #pragma unroll
        for (int kk = 0; kk < 2; kk++) {
            uint32_t bh[4][2], bl[4][2];
            #pragma unroll
            for (int np = 0; np < 2; np++) {
                const uint32_t row = wn * 32 + np * 16 + ((lane >> 4) & 1) * 8 + (lane & 7);
                const uint32_t off = row * ROWB + kk * 32 + ((lane >> 3) & 1) * 16;
                ldsm4(bh[np*2][0], bh[np*2][1], bh[np*2+1][0], bh[np*2+1][1], bBh + off);
                if (TERMS == 3)
                    ldsm4(bl[np*2][0], bl[np*2][1], bl[np*2+1][0], bl[np*2+1][1], bBl + off);
            }
            #pragma unroll
            for (int mt = 0; mt < 4; mt++) {
                const uint32_t row = wm * 64 + mt * 16 + (lane & 15);
                const uint32_t off = row * ROWB + kk * 32 + (lane >> 4) * 16;
                uint32_t ah0, ah1, ah2, ah3;
                ldsm4(ah0, ah1, ah2, ah3, bAh + off);
                if (TERMS == 3) {
                    uint32_t al0, al1, al2, al3;
                    ldsm4(al0, al1, al2, al3, bAl + off);
                    #pragma unroll
                    for (int nt = 0; nt < 4; nt++) {
                        mma_bf16(acc[mt][nt], ah0, ah1, ah2, ah3, bh[nt][0], bh[nt][1]);
                        mma_bf16(acc[mt][nt], ah0, ah1, ah2, ah3, bl[nt][0], bl[nt][1]);
                        mma_bf16(acc[mt][nt], al0, al1, al2, al3, bh[nt][0], bh[nt][1]);
                    }
                } else {
                    #pragma unroll
                    for (int nt = 0; nt < 4; nt++)
                        mma_bf16(acc[mt][nt], ah0, ah1, ah2, ah3, bh[nt][0], bh[nt][1]);
                }
            }
        }
    };

    const int iters = K / 32;
    load_slab(0, 0); CPCOMMIT();
    load_slab(1, 1); CPCOMMIT();
    CPWAIT1();
    __syncthreads();

    for (int i = 0; i < iters; i++) {
        const int s = i & 1;
        compute(s);
        __syncthreads();
        if (i + 2 < iters) { load_slab(i + 2, s); CPCOMMIT(); }
        if (i + 1 < iters) {
            if (i + 2 < iters) CPWAIT1(); else CPWAIT0();
            __syncthreads();
        }
    }

    // ---- epilogue from registers ----
    #pragma unroll
    for (int mt = 0; mt < 4; mt++) {
        #pragma unroll
        for (int nt = 0; nt < 4; nt++) {
            const int m = m0 + wm * 64 + mt * 16 + g;
            const int n = n0 + wn * 32 + nt * 8 + 2 * t;
            float* c = acc[mt][nt];
            #pragma unroll
            for (int half = 0; half < 2; half++) {
                const int mm = m + half * 8;
                const long idx = (long)mm * N + n;
                float x0 = c[half * 2 + 0];
                float x1 = c[half * 2 + 1];
                if (MODE == 0 || MODE == 1 || MODE == 4) { x0 += bias[n]; x1 += bias[n + 1]; }
                if (MODE == 1) { x0 = fmaxf(x0, 0.0f); x1 = fmaxf(x1, 0.0f); }
                if (MODE == 2) { x0 *= alpha; x1 *= alpha; }
                if (MODE == 4) {
                    float g0 = 1.0f / (1.0f + __expf(-x0));
                    g0 = 1.0f / (1.0f + __expf(-g0));
                    float g1 = 1.0f / (1.0f + __expf(-x1));
                    g1 = 1.0f / (1.0f + __expf(-g1));
                    x0 = g0 * att[idx]     * ts[n];
                    x1 = g1 * att[idx + 1] * ts[n + 1];
                }
                if (MODE == 2 || MODE == 3 || MODE == 4)
                    *(float2*)&Cf[(long)z * sC + idx] = make_float2(x0, x1);
                if (MODE == 0 || MODE == 3) {
                    bf16 h0 = __float2bfloat16_rn(x0);
                    bf16 h1 = __float2bfloat16_rn(x1);
                    bf16 l0 = __float2bfloat16_rn(x0 - __bfloat162float(h0));
                    bf16 l1 = __float2bfloat16_rn(x1 - __bfloat162float(h1));
                    uint32_t hw = (uint32_t)__bfloat16_as_ushort(h0)
                                | ((uint32_t)__bfloat16_as_ushort(h1) << 16);
                    uint32_t lw = (uint32_t)__bfloat16_as_ushort(l0)
                                | ((uint32_t)__bfloat16_as_ushort(l1) << 16);
                    *(uint32_t*)&Ch[(long)z * sC + idx] = hw;
                    *(uint32_t*)&Cl[(long)z * sC + idx] = lw;
                }
                if (MODE == 1) {
                    bf16 h0 = __float2bfloat16_rn(x0);
                    bf16 h1 = __float2bfloat16_rn(x1);
                    uint32_t hw = (uint32_t)__bfloat16_as_ushort(h0)
                                | ((uint32_t)__bfloat16_as_ushort(h1) << 16);
                    *(uint32_t*)&Ch[(long)z * sC + idx] = hw;
                }
            }
        }
    }
}

// ---------------- fp32 -> bf16 hi/lo split ----------------
__global__ __launch_bounds__(256) void split_k(const float* __restrict__ x,
                                               bf16* __restrict__ hi, bf16* __restrict__ lo,
                                               long n)
{
    long i = ((long)blockIdx.x * 256 + threadIdx.x) * 4;
    if (i >= n) return;
    float4 v = *(const float4*)&x[i];
    float a[4] = {v.x, v.y, v.z, v.w};
    uint32_t hw[2], lw[2];
    #pragma unroll
    for (int p = 0; p < 2; p++) {
        bf16 h0 = __float2bfloat16_rn(a[2*p]);
        bf16 h1 = __float2bfloat16_rn(a[2*p+1]);
        bf16 l0 = __float2bfloat16_rn(a[2*p]   - __bfloat162float(h0));
        bf16 l1 = __float2bfloat16_rn(a[2*p+1] - __bfloat162float(h1));
        hw[p] = (uint32_t)__bfloat16_as_ushort(h0) | ((uint32_t)__bfloat16_as_ushort(h1) << 16);
        lw[p] = (uint32_t)__bfloat16_as_ushort(l0) | ((uint32_t)__bfloat16_as_ushort(l1) << 16);
    }
    *(uint2*)&hi[i] = make_uint2(hw[0], hw[1]);
    *(uint2*)&lo[i] = make_uint2(lw[0], lw[1]);
}

// ---------------- V transpose (per batch): [S,D] -> [D,S] ----------------
__global__ __launch_bounds__(256) void transp_k(const bf16* __restrict__ vh,
                                                const bf16* __restrict__ vl,
                                                bf16* __restrict__ oh, bf16* __restrict__ ol)
{
    __shared__ bf16 th[32][33], tl[32][33];
    const int b = blockIdx.z;
    const int d0 = blockIdx.x * 32, s0 = blockIdx.y * 32;
    const int tx = threadIdx.x, ty = threadIdx.y;
    #pragma unroll
    for (int j = 0; j < 32; j += 8) {
        const long src = ((long)b * SLEN + s0 + ty + j) * DCOL + d0 + tx;
        th[ty + j][tx] = vh[src];
        tl[ty + j][tx] = vl[src];
    }
    __syncthreads();
    #pragma unroll
    for (int j = 0; j < 32; j += 8) {
        const long dst = ((long)b * DCOL + d0 + ty + j) * SLEN + s0 + tx;
        oh[dst] = th[tx][ty + j];
        ol[dst] = tl[tx][ty + j];
    }
}

// ---------------- row softmax (2048) -> bf16 hi/lo P ----------------
__global__ __launch_bounds__(256) void softmax_k(const float* __restrict__ S,
                                                 bf16* __restrict__ ph, bf16* __restrict__ pl)
{
    const float* p = S + (long)blockIdx.x * SLEN;
    bf16* oh = ph + (long)blockIdx.x * SLEN;
    bf16* ol = pl + (long)blockIdx.x * SLEN;
    const int tid = threadIdx.x;
    const int lane = tid & 31, wid = tid >> 5;
    __shared__ float red[8];

    float v[8];
    float mx = -INFINITY;
    #pragma unroll
    for (int i = 0; i < 8; i++) { v[i] = p[tid + 256 * i]; mx = fmaxf(mx, v[i]); }
    #pragma unroll
    for (int o = 16; o > 0; o >>= 1) mx = fmaxf(mx, __shfl_xor_sync(~0u, mx, o));
    if (lane == 0) red[wid] = mx;
    __syncthreads();
    { float m2 = red[lane & 7];
      #pragma unroll
      for (int o = 4; o > 0; o >>= 1) m2 = fmaxf(m2, __shfl_xor_sync(~0u, m2, o));
      mx = __shfl_sync(~0u, m2, 0); }
    float sum = 0.0f;
    #pragma unroll
    for (int i = 0; i < 8; i++) { v[i] = __expf(v[i] - mx); sum += v[i]; }
    #pragma unroll
    for (int o = 16; o > 0; o >>= 1) sum += __shfl_xor_sync(~0u, sum, o);
    __syncthreads();
    if (lane == 0) red[wid] = sum;
    __syncthreads();
    { float s2 = red[lane & 7];
      #pragma unroll
      for (int o = 4; o > 0; o >>= 1) s2 += __shfl_xor_sync(~0u, s2, o);
      sum = __shfl_sync(~0u, s2, 0); }
    const float inv = 1.0f / sum;
    #pragma unroll
    for (int i = 0; i < 8; i++) {
        float r = v[i] * inv;
        bf16 h = __float2bfloat16_rn(r);
        oh[tid + 256 * i] = h;
        ol[tid + 256 * i] = __float2bfloat16_rn(r - __bfloat162float(h));
    }
}

// ---------------------------------------------------------------
extern "C" void kernel_launch(void* const* d_in, const int* in_sizes, int n_in,
                              void* d_out, int out_size)
{
    const float* query = (const float*)d_in[0];
    const float* key   = (const float*)d_in[1];
    const float* value = (const float*)d_in[2];
    const float* W[5]  = {(const float*)d_in[3], (const float*)d_in[5], (const float*)d_in[7],
                          (const float*)d_in[9], (const float*)d_in[11]};
    const float* bq  = (const float*)d_in[4];
    const float* bk  = (const float*)d_in[6];
    const float* bv  = (const float*)d_in[8];
    const float* bg1 = (const float*)d_in[10];
    const float* bg2 = (const float*)d_in[12];
    const float* ts  = (const float*)d_in[13];
    float* out = (float*)d_out;

    bf16 *xh, *xl, *wh, *wl, *ah, *al, *vth, *vtl, *ph, *pl;
    float *attf, *sf;
    cudaGetSymbolAddress((void**)&xh,  g_xh);
    cudaGetSymbolAddress((void**)&xl,  g_xl);
    cudaGetSymbolAddress((void**)&wh,  g_wh);
    cudaGetSymbolAddress((void**)&wl,  g_wl);
    cudaGetSymbolAddress((void**)&ah,  g_ah);
    cudaGetSymbolAddress((void**)&al,  g_al);
    cudaGetSymbolAddress((void**)&vth, g_vth);
    cudaGetSymbolAddress((void**)&vtl, g_vtl);
    cudaGetSymbolAddress((void**)&attf, g_att);
    cudaGetSymbolAddress((void**)&sf,   g_s);
    cudaGetSymbolAddress((void**)&ph,  g_ph);
    cudaGetSymbolAddress((void**)&pl,  g_pl);

    cudaFuncSetAttribute(gemm_m<0,3>, cudaFuncAttributeMaxDynamicSharedMemorySize, SMEM_BYTES);
    cudaFuncSetAttribute(gemm_m<2,3>, cudaFuncAttributeMaxDynamicSharedMemorySize, SMEM_BYTES);
    cudaFuncSetAttribute(gemm_m<3,3>, cudaFuncAttributeMaxDynamicSharedMemorySize, SMEM_BYTES);
    cudaFuncSetAttribute(gemm_m<1,1>, cudaFuncAttributeMaxDynamicSharedMemorySize, SMEM_BYTES);
    cudaFuncSetAttribute(gemm_m<4,1>, cudaFuncAttributeMaxDynamicSharedMemorySize, SMEM_BYTES);

    const size_t NX = (size_t)MTOK * DCOL;
    const size_t NW = (size_t)DCOL * DCOL;

    // 1) split inputs + weights to bf16 hi/lo
    const float* xin[3] = {query, key, value};
    for (int i = 0; i < 3; i++)
        split_k<<<(int)(NX / 4 / 256), 256>>>(xin[i], xh + i * NX, xl + i * NX, (long)NX);
    for (int i = 0; i < 5; i++)
        split_k<<<(int)((NW / 4 + 255) / 256), 256>>>(W[i], wh + i * NW, wl + i * NW, (long)NW);

    const dim3 blk(256);
    const dim3 gproj(DCOL / 128, MTOK / 128, 1);
    const dim3 gsc(SLEN / 128, SLEN / 128, BATCH);
    const dim3 gat(DCOL / 128, SLEN / 128, BATCH);

    // 2) Q/K/V projections (3-term)
    const float* bias3[3] = {bq, bk, bv};
    for (int i = 0; i < 3; i++)
        gemm_m<0,3><<<gproj, blk, SMEM_BYTES>>>(
            xh + i * NX, xl + i * NX, wh + i * NW, wl + i * NW,
            MTOK, DCOL, DCOL, 0, 0, 0, bias3[i], 1.0f,
            nullptr, ah + i * NX, al + i * NX, nullptr, nullptr);

    // 3) transpose V
    transp_k<<<dim3(DCOL / 32, SLEN / 32, BATCH), dim3(32, 8)>>>(
        ah + 2 * NX, al + 2 * NX, vth, vtl);

    // 4) scores = (Q @ K^T) * scale (3-term)
    const float scale = 1.0f / sqrtf((float)DCOL);
    gemm_m<2,3><<<gsc, blk, SMEM_BYTES>>>(
        ah + 0 * NX, al + 0 * NX, ah + 1 * NX, al + 1 * NX,
        SLEN, SLEN, DCOL, (long)SLEN * DCOL, (long)SLEN * DCOL, (long)SLEN * SLEN,
        nullptr, scale, sf, nullptr, nullptr, nullptr, nullptr);

    // 5) softmax -> P hi/lo
    softmax_k<<<MTOK, 256>>>(sf, ph, pl);

    // 6) attended = P @ V (3-term)
    gemm_m<3,3><<<gat, blk, SMEM_BYTES>>>(
        ph, pl, vth, vtl,
        SLEN, DCOL, SLEN, (long)SLEN * SLEN, (long)DCOL * SLEN, (long)SLEN * DCOL,
        nullptr, 1.0f, attf, ah + 3 * NX, al + 3 * NX, nullptr, nullptr);

    // 7) h = relu(att @ Wg1^T + bg1)  (1-term: double-sigmoid attenuates error)
    gemm_m<1,1><<<gproj, blk, SMEM_BYTES>>>(
        ah + 3 * NX, nullptr, wh + 3 * NW, nullptr,
        MTOK, DCOL, DCOL, 0, 0, 0, bg1, 1.0f,
        nullptr, ah + 4 * NX, nullptr, nullptr, nullptr);

    // 8) out = sig(sig(h @ Wg2^T + bg2)) * att * ts  (1-term)
    gemm_m<4,1><<<gproj, blk, SMEM_BYTES>>>(
        ah + 4 * NX, nullptr, wh + 4 * NW, nullptr,
        MTOK, DCOL, DCOL, 0, 0, 0, bg2, 1.0f,
        out, nullptr, nullptr, attf, ts);
}